// round 7
// baseline (speedup 1.0000x reference)
#include <cuda_runtime.h>
#include <cuda_fp16.h>
#include <cstdint>

#define NMAX 50000
#define EMAX 800000
#define F 144
#define NB_SCAN 128

typedef unsigned long long ull;
typedef unsigned int uint;

// ---- scratch (no allocations allowed; __device__ globals) ----
__device__ int    g_deg[NMAX];
__device__ float  g_dinv[NMAX];
__device__ int    g_rowptr[NMAX + 1];
__device__ int    g_cursor[NMAX];
__device__ int2   g_edge[EMAX];                  // {col, valbits}
__device__ int    g_chain[NB_SCAN];              // chained-scan partials
__device__ int    g_chflag[NB_SCAN];             // chained-scan flags
__device__ float4 g_tx1[(size_t)NMAX * 36];      // Tx1 fp32 (GEMM operand)
__device__ float4 g_tx2[(size_t)NMAX * 36];      // z = L*Tx1 fp32 (GEMM operand)
__device__ uint2  g_xh [(size_t)NMAX * 36];      // x   fp16 (gather copy)
__device__ uint2  g_t1h[(size_t)NMAX * 36];      // Tx1 fp16 (gather copy)
__device__ float  g_wcat[432 * 144];             // [W0-W2 ; W1 ; 2*W2]

// ---------------------------------------------------------------------------
// 1) prep: zero deg, reset scan flags, x -> fp16, build concatenated weights
// ---------------------------------------------------------------------------
__global__ void prep_kernel(const float* __restrict__ x,
                            const float* __restrict__ wgt, int n) {
    int i = blockIdx.x * blockDim.x + threadIdx.x;
    if (i < n) g_deg[i] = 0;
    if (i < NB_SCAN) g_chflag[i] = 0;
    if (i < 432 * 144) {
        int k = i / 144, j = i % 144;
        float v;
        if (k < 144)      v = wgt[i] - wgt[(288 + k) * 144 + j];
        else if (k < 288) v = wgt[i];
        else              v = 2.0f * wgt[i];
        g_wcat[i] = v;
    }
    // x convert: one half2 (two floats) per index
    int nh = n * 72;
    if (i < nh) {
        float2 f = *reinterpret_cast<const float2*>(x + 2 * i);
        __half2 h = __floats2half2_rn(f.x, f.y);
        reinterpret_cast<uint*>(g_xh)[i] = *reinterpret_cast<uint*>(&h);
    }
}

// ---------------------------------------------------------------------------
// 2) degree histogram (self-loops masked)
// ---------------------------------------------------------------------------
__global__ void hist4_kernel(const int* __restrict__ row, const int* __restrict__ col, int e) {
    int i = (blockIdx.x * blockDim.x + threadIdx.x) * 4;
    if (i + 4 <= e) {
        int4 r = *reinterpret_cast<const int4*>(row + i);
        int4 c = *reinterpret_cast<const int4*>(col + i);
        if (r.x != c.x) atomicAdd(&g_deg[r.x], 1);
        if (r.y != c.y) atomicAdd(&g_deg[r.y], 1);
        if (r.z != c.z) atomicAdd(&g_deg[r.z], 1);
        if (r.w != c.w) atomicAdd(&g_deg[r.w], 1);
    } else {
        for (; i < e; ++i) {
            int r = row[i];
            if (r != col[i]) atomicAdd(&g_deg[r], 1);
        }
    }
}

// ---------------------------------------------------------------------------
// 3) chained scan: rowptr/cursor/dinv in ONE kernel (all blocks resident)
// ---------------------------------------------------------------------------
__global__ void scan_chain_kernel(int n) {
    __shared__ int sm[512];
    __shared__ int base;
    int t = threadIdx.x, b = blockIdx.x, i = b * 512 + t;
    int d = (i < n) ? g_deg[i] : 0;
    sm[t] = d;
    __syncthreads();
#pragma unroll
    for (int off = 1; off < 512; off <<= 1) {
        int v = (t >= off) ? sm[t - off] : 0;
        __syncthreads();
        sm[t] += v;
        __syncthreads();
    }
    if (t == 0) {
        int pb = 0;
        if (b > 0) {
            volatile int* vf = g_chflag;
            while (vf[b - 1] == 0) { }
            __threadfence();
            pb = *((volatile int*)&g_chain[b - 1]);
        }
        *((volatile int*)&g_chain[b]) = pb + sm[511];
        __threadfence();
        *((volatile int*)&g_chflag[b]) = 1;
        base = pb;
    }
    __syncthreads();
    if (i < n) {
        int excl = base + sm[t] - d;
        g_rowptr[i] = excl;
        g_cursor[i] = excl;
        g_dinv[i] = (d > 0) ? rsqrtf((float)d) : 0.0f;
        if (i == n - 1) g_rowptr[n] = excl + d;
    }
}

// ---------------------------------------------------------------------------
// 4) scatter edges into CSR (4 edges/thread for MLP)
// ---------------------------------------------------------------------------
__global__ void scatter4_kernel(const int* __restrict__ row, const int* __restrict__ col,
                                const float* __restrict__ w, int e) {
    int i = (blockIdx.x * blockDim.x + threadIdx.x) * 4;
    if (i + 4 <= e) {
        int4 r = *reinterpret_cast<const int4*>(row + i);
        int4 c = *reinterpret_cast<const int4*>(col + i);
        float4 ww = *reinterpret_cast<const float4*>(w + i);
        float dr0 = g_dinv[r.x], dc0 = g_dinv[c.x];
        float dr1 = g_dinv[r.y], dc1 = g_dinv[c.y];
        float dr2 = g_dinv[r.z], dc2 = g_dinv[c.z];
        float dr3 = g_dinv[r.w], dc3 = g_dinv[c.w];
        if (r.x != c.x) {
            int p = atomicAdd(&g_cursor[r.x], 1);
            g_edge[p] = make_int2(c.x, __float_as_int(-dr0 * ww.x * dc0));
        }
        if (r.y != c.y) {
            int p = atomicAdd(&g_cursor[r.y], 1);
            g_edge[p] = make_int2(c.y, __float_as_int(-dr1 * ww.y * dc1));
        }
        if (r.z != c.z) {
            int p = atomicAdd(&g_cursor[r.z], 1);
            g_edge[p] = make_int2(c.z, __float_as_int(-dr2 * ww.z * dc2));
        }
        if (r.w != c.w) {
            int p = atomicAdd(&g_cursor[r.w], 1);
            g_edge[p] = make_int2(c.w, __float_as_int(-dr3 * ww.w * dc3));
        }
    } else {
        for (; i < e; ++i) {
            int r = row[i], c = col[i];
            if (r != c) {
                int p = atomicAdd(&g_cursor[r], 1);
                g_edge[p] = make_int2(c, __float_as_int(-g_dinv[r] * w[i] * g_dinv[c]));
            }
        }
    }
}

// ---------------------------------------------------------------------------
// 5) SpMM with fp16 gathers, fp32 accumulate
//    pass 0: tx1 = L @ x   (gathers g_xh,  writes g_tx1 fp32 + g_t1h fp16)
//    pass 1: z   = L @ tx1 (gathers g_t1h, writes g_tx2 fp32)
// ---------------------------------------------------------------------------
__device__ __forceinline__ float4 h2f4(uint2 u) {
    __half2 h0 = *reinterpret_cast<__half2*>(&u.x);
    __half2 h1 = *reinterpret_cast<__half2*>(&u.y);
    float2 a = __half22float2(h0);
    float2 b = __half22float2(h1);
    return make_float4(a.x, a.y, b.x, b.y);
}
__device__ __forceinline__ void facc(float4& acc, float w, float4 v) {
    acc.x = fmaf(w, v.x, acc.x); acc.y = fmaf(w, v.y, acc.y);
    acc.z = fmaf(w, v.z, acc.z); acc.w = fmaf(w, v.w, acc.w);
}

__global__ void spmm_kernel(int n, int pass) {
    int r = blockIdx.x * 8 + threadIdx.y;
    if (r >= n) return;
    int lane = threadIdx.x;  // 0..35

    const uint2* __restrict__ src = pass ? g_t1h : g_xh;

    int s = g_rowptr[r];
    int e = g_rowptr[r + 1];

    float4 acc = make_float4(0.f, 0.f, 0.f, 0.f);
    int i = s;
    for (; i + 4 <= e; i += 4) {
        int2 e0 = __ldg(&g_edge[i + 0]);
        int2 e1 = __ldg(&g_edge[i + 1]);
        int2 e2 = __ldg(&g_edge[i + 2]);
        int2 e3 = __ldg(&g_edge[i + 3]);
        uint2 u0 = __ldg(&src[(size_t)e0.x * 36 + lane]);
        uint2 u1 = __ldg(&src[(size_t)e1.x * 36 + lane]);
        uint2 u2 = __ldg(&src[(size_t)e2.x * 36 + lane]);
        uint2 u3 = __ldg(&src[(size_t)e3.x * 36 + lane]);
        facc(acc, __int_as_float(e0.y), h2f4(u0));
        facc(acc, __int_as_float(e1.y), h2f4(u1));
        facc(acc, __int_as_float(e2.y), h2f4(u2));
        facc(acc, __int_as_float(e3.y), h2f4(u3));
    }
    for (; i < e; ++i) {
        int2 ee = __ldg(&g_edge[i]);
        uint2 u = __ldg(&src[(size_t)ee.x * 36 + lane]);
        facc(acc, __int_as_float(ee.y), h2f4(u));
    }

    size_t o = (size_t)r * 36 + lane;
    if (pass) {
        g_tx2[o] = acc;                       // z = L*Tx1 (fold 2x into W2')
    } else {
        g_tx1[o] = acc;
        __half2 h01 = __floats2half2_rn(acc.x, acc.y);
        __half2 h23 = __floats2half2_rn(acc.z, acc.w);
        uint2 u;
        u.x = *reinterpret_cast<uint*>(&h01);
        u.y = *reinterpret_cast<uint*>(&h23);
        g_t1h[o] = u;
    }
}

// ---------------------------------------------------------------------------
// 6) fused GEMM: out[N,144] = [x|tx1|z] @ g_wcat + bias
//    BM=128, BK=24, 384 threads, 4x12 micro-tile, packed f32x2 FMA
// ---------------------------------------------------------------------------
#define BM 128
#define GT 384

__device__ __forceinline__ ull fdup(float v) {
    unsigned u = __float_as_uint(v);
    return (ull)u | ((ull)u << 32);
}
__device__ __forceinline__ void ffma2(ull& d, ull a, ull b) {
    asm("fma.rn.f32x2 %0, %1, %2, %0;" : "+l"(d) : "l"(a), "l"(b));
}

__global__ __launch_bounds__(GT) void gemm_kernel(const float* __restrict__ x,
                                                  const float* __restrict__ bias,
                                                  float* __restrict__ out, int n) {
    __shared__ __align__(16) ull   As[24 * 130];
    __shared__ __align__(16) float Bs[24 * 148];

    int tid = threadIdx.x;
    int m0 = blockIdx.x * BM;
    int cg = tid % 12;
    int rg = tid / 12;
    int colS = 12 * cg + ((cg >= 8) ? 2 : 0);
    int colG = 12 * cg;

    int qa0 = tid % 6,         ma0 = tid / 6;
    int qa1 = (GT + tid) % 6,  ma1 = (GT + tid) / 6;
    int physb[9];
#pragma unroll
    for (int p = 0; p < 9; ++p) {
        int idx = p * GT + tid;
        int j = idx % 144, kk = idx / 144;
        physb[p] = kk * 148 + j + ((j >= 96) ? 2 : 0);
    }

    ull acc[4][6];
#pragma unroll
    for (int r = 0; r < 4; ++r)
#pragma unroll
        for (int p = 0; p < 6; ++p) acc[r][p] = 0ull;

    const float* t1 = (const float*)g_tx1;
    const float* t2 = (const float*)g_tx2;

    float4 av0, av1;
    float bv[9];

    {   // prefetch kt = 0
        int gm0 = m0 + ma0, gm1 = m0 + ma1;
        av0 = (gm0 < n) ? *reinterpret_cast<const float4*>(x + (size_t)gm0 * 144 + 4 * qa0)
                        : make_float4(0.f, 0.f, 0.f, 0.f);
        av1 = (gm1 < n) ? *reinterpret_cast<const float4*>(x + (size_t)gm1 * 144 + 4 * qa1)
                        : make_float4(0.f, 0.f, 0.f, 0.f);
#pragma unroll
        for (int p = 0; p < 9; ++p) bv[p] = g_wcat[p * GT + tid];
    }

    for (int kt = 0; kt < 18; ++kt) {
        As[(4 * qa0 + 0) * 130 + ma0] = fdup(av0.x);
        As[(4 * qa0 + 1) * 130 + ma0] = fdup(av0.y);
        As[(4 * qa0 + 2) * 130 + ma0] = fdup(av0.z);
        As[(4 * qa0 + 3) * 130 + ma0] = fdup(av0.w);
        As[(4 * qa1 + 0) * 130 + ma1] = fdup(av1.x);
        As[(4 * qa1 + 1) * 130 + ma1] = fdup(av1.y);
        As[(4 * qa1 + 2) * 130 + ma1] = fdup(av1.z);
        As[(4 * qa1 + 3) * 130 + ma1] = fdup(av1.w);
#pragma unroll
        for (int p = 0; p < 9; ++p) Bs[physb[p]] = bv[p];
        __syncthreads();

        if (kt < 17) {
            int kn = kt + 1;
            int s = kn / 6;
            int kl = (kn % 6) * 24;
            const float* A = (s == 0) ? x : ((s == 1) ? t1 : t2);
            int gm0 = m0 + ma0, gm1 = m0 + ma1;
            av0 = (gm0 < n) ? *reinterpret_cast<const float4*>(A + (size_t)gm0 * 144 + kl + 4 * qa0)
                            : make_float4(0.f, 0.f, 0.f, 0.f);
            av1 = (gm1 < n) ? *reinterpret_cast<const float4*>(A + (size_t)gm1 * 144 + kl + 4 * qa1)
                            : make_float4(0.f, 0.f, 0.f, 0.f);
            const float* Wt = g_wcat + (size_t)kn * 3456;
#pragma unroll
            for (int p = 0; p < 9; ++p) bv[p] = __ldg(&Wt[p * GT + tid]);
        }

#pragma unroll
        for (int kk = 0; kk < 24; ++kk) {
            const ull* ar = &As[kk * 130 + rg * 4];
            ulonglong2 A01 = *reinterpret_cast<const ulonglong2*>(ar);
            ulonglong2 A23 = *reinterpret_cast<const ulonglong2*>(ar + 2);
            ull a0 = A01.x, a1 = A01.y, a2 = A23.x, a3 = A23.y;
            const float* bp = &Bs[kk * 148 + colS];
            ull b0 = *reinterpret_cast<const ull*>(bp);
            ull b1 = *reinterpret_cast<const ull*>(bp + 2);
            ull b2 = *reinterpret_cast<const ull*>(bp + 4);
            ull b3 = *reinterpret_cast<const ull*>(bp + 6);
            ull b4 = *reinterpret_cast<const ull*>(bp + 8);
            ull b5 = *reinterpret_cast<const ull*>(bp + 10);
            ffma2(acc[0][0], a0, b0); ffma2(acc[0][1], a0, b1); ffma2(acc[0][2], a0, b2);
            ffma2(acc[0][3], a0, b3); ffma2(acc[0][4], a0, b4); ffma2(acc[0][5], a0, b5);
            ffma2(acc[1][0], a1, b0); ffma2(acc[1][1], a1, b1); ffma2(acc[1][2], a1, b2);
            ffma2(acc[1][3], a1, b3); ffma2(acc[1][4], a1, b4); ffma2(acc[1][5], a1, b5);
            ffma2(acc[2][0], a2, b0); ffma2(acc[2][1], a2, b1); ffma2(acc[2][2], a2, b2);
            ffma2(acc[2][3], a2, b3); ffma2(acc[2][4], a2, b4); ffma2(acc[2][5], a2, b5);
            ffma2(acc[3][0], a3, b0); ffma2(acc[3][1], a3, b1); ffma2(acc[3][2], a3, b2);
            ffma2(acc[3][3], a3, b3); ffma2(acc[3][4], a3, b4); ffma2(acc[3][5], a3, b5);
        }
        __syncthreads();
    }

    float bl[12];
#pragma unroll
    for (int t = 0; t < 12; ++t) bl[t] = __ldg(&bias[colG + t]);

#pragma unroll
    for (int r = 0; r < 4; ++r) {
        int gm = m0 + rg * 4 + r;
        if (gm < n) {
            float* o = out + (size_t)gm * 144 + colG;
#pragma unroll
            for (int q = 0; q < 3; ++q) {
                ull p0 = acc[r][2 * q], p1 = acc[r][2 * q + 1];
                float4 v;
                v.x = __uint_as_float((unsigned)(p0 & 0xffffffffu)) + bl[4 * q + 0];
                v.y = __uint_as_float((unsigned)(p0 >> 32))         + bl[4 * q + 1];
                v.z = __uint_as_float((unsigned)(p1 & 0xffffffffu)) + bl[4 * q + 2];
                v.w = __uint_as_float((unsigned)(p1 >> 32))         + bl[4 * q + 3];
                *reinterpret_cast<float4*>(o + 4 * q) = v;
            }
        }
    }
}

// ---------------------------------------------------------------------------
// launcher
// ---------------------------------------------------------------------------
extern "C" void kernel_launch(void* const* d_in, const int* in_sizes, int n_in,
                              void* d_out, int out_size) {
    const float* x    = (const float*)d_in[0];   // [N, 144]
    const int*   ei   = (const int*)d_in[1];     // [2, E]
    const float* ew   = (const float*)d_in[2];   // [E]
    const float* wgt  = (const float*)d_in[3];   // [3, 144, 144]
    const float* bias = (const float*)d_in[4];   // [144]
    float* out = (float*)d_out;

    int n = in_sizes[0] / F;
    int e = in_sizes[2];
    const int* row = ei;
    const int* col = ei + e;
    int nb = (n + 511) / 512;   // <= 98 for N=50000, fits resident

    prep_kernel<<<(n * 72 + 255) / 256, 256>>>(x, wgt, n);
    hist4_kernel<<<((e + 3) / 4 + 255) / 256, 256>>>(row, col, e);
    scan_chain_kernel<<<nb, 512>>>(n);
    scatter4_kernel<<<((e + 3) / 4 + 255) / 256, 256>>>(row, col, ew, e);

    dim3 sb(36, 8);
    spmm_kernel<<<(n + 7) / 8, sb>>>(n, 0);   // tx1 = L x      (fp16 gather)
    spmm_kernel<<<(n + 7) / 8, sb>>>(n, 1);   // z   = L tx1    (fp16 gather)

    gemm_kernel<<<(n + BM - 1) / BM, GT>>>(x, bias, out, n);
}

// round 9
// speedup vs baseline: 1.4532x; 1.4532x over previous
#include <cuda_runtime.h>
#include <cuda_fp16.h>
#include <cstdint>

#define NMAX 50000
#define EMAX 800000
#define F 144

typedef unsigned long long ull;
typedef unsigned int uint;

// ---- scratch (no allocations allowed; __device__ globals) ----
__device__ int    g_deg[NMAX];
__device__ float  g_dinv[NMAX];
__device__ int    g_rowptr[NMAX + 1];
__device__ int    g_cursor[NMAX];
__device__ int2   g_edge[EMAX];                  // {col, valbits}
__device__ int    g_bsum[128];
__device__ int    g_boff[128];
__device__ float4 g_tx1[(size_t)NMAX * 36];      // Tx1 fp32 (GEMM operand)
__device__ float4 g_tx2[(size_t)NMAX * 36];      // z = L*Tx1 fp32 (GEMM operand)
__device__ uint2  g_xh [(size_t)NMAX * 36];      // x   fp16 (gather copy)
__device__ uint2  g_t1h[(size_t)NMAX * 36];      // Tx1 fp16 (gather copy)
__device__ float  g_wcat[432 * 144];             // [W0-W2 ; W1 ; 2*W2]

// register-only fp16x2 -> float2 (no address-of, cannot spill)
__device__ __forceinline__ float2 h2tof2(uint h) {
    float2 r;
    asm("{\n\t"
        ".reg .b16 lo, hi;\n\t"
        "mov.b32 {lo, hi}, %2;\n\t"
        "cvt.f32.f16 %0, lo;\n\t"
        "cvt.f32.f16 %1, hi;\n\t"
        "}" : "=f"(r.x), "=f"(r.y) : "r"(h));
    return r;
}
// register-only float,float -> fp16x2 (hi goes to high half)
__device__ __forceinline__ uint f2toh2(float lo, float hi) {
    uint u;
    asm("cvt.rn.f16x2.f32 %0, %1, %2;" : "=r"(u) : "f"(hi), "f"(lo));
    return u;
}

// ---------------------------------------------------------------------------
// 1) prep: zero deg, build concatenated weights, x -> fp16
// ---------------------------------------------------------------------------
__global__ void prep_kernel(const float* __restrict__ x,
                            const float* __restrict__ wgt, int n) {
    int i = blockIdx.x * blockDim.x + threadIdx.x;
    if (i < n) g_deg[i] = 0;
    if (i < 432 * 144) {
        int k = i / 144, j = i % 144;
        float v;
        if (k < 144)      v = wgt[i] - wgt[(288 + k) * 144 + j];
        else if (k < 288) v = wgt[i];
        else              v = 2.0f * wgt[i];
        g_wcat[i] = v;
    }
    int nh = n * 72;   // one fp16x2 word per thread
    if (i < nh) {
        float2 f = *reinterpret_cast<const float2*>(x + 2 * i);
        reinterpret_cast<uint*>(g_xh)[i] = f2toh2(f.x, f.y);
    }
}

// ---------------------------------------------------------------------------
// 2) degree histogram (self-loops masked)
// ---------------------------------------------------------------------------
__global__ void hist4_kernel(const int* __restrict__ row, const int* __restrict__ col, int e) {
    int i = (blockIdx.x * blockDim.x + threadIdx.x) * 4;
    if (i + 4 <= e) {
        int4 r = *reinterpret_cast<const int4*>(row + i);
        int4 c = *reinterpret_cast<const int4*>(col + i);
        if (r.x != c.x) atomicAdd(&g_deg[r.x], 1);
        if (r.y != c.y) atomicAdd(&g_deg[r.y], 1);
        if (r.z != c.z) atomicAdd(&g_deg[r.z], 1);
        if (r.w != c.w) atomicAdd(&g_deg[r.w], 1);
    } else {
        for (; i < e; ++i) {
            int r = row[i];
            if (r != col[i]) atomicAdd(&g_deg[r], 1);
        }
    }
}

// ---------------------------------------------------------------------------
// 3) 3-kernel scan (R6 proven): reduce, block-scan, local scan + offset
// ---------------------------------------------------------------------------
__global__ void scanA_kernel(int n) {
    __shared__ int sm[512];
    int t = threadIdx.x, i = blockIdx.x * 512 + t;
    sm[t] = (i < n) ? g_deg[i] : 0;
    __syncthreads();
    for (int off = 256; off > 0; off >>= 1) {
        if (t < off) sm[t] += sm[t + off];
        __syncthreads();
    }
    if (t == 0) g_bsum[blockIdx.x] = sm[0];
}

__global__ void scanB_kernel(int nb) {
    __shared__ int sm[128];
    int t = threadIdx.x;
    sm[t] = (t < nb) ? g_bsum[t] : 0;
    __syncthreads();
    for (int off = 1; off < 128; off <<= 1) {
        int v = (t >= off) ? sm[t - off] : 0;
        __syncthreads();
        sm[t] += v;
        __syncthreads();
    }
    if (t < nb) g_boff[t] = t ? sm[t - 1] : 0;
}

__global__ void scanC_kernel(int n) {
    __shared__ int sm[512];
    int t = threadIdx.x, b = blockIdx.x, i = b * 512 + t;
    int d = (i < n) ? g_deg[i] : 0;
    sm[t] = d;
    __syncthreads();
    for (int off = 1; off < 512; off <<= 1) {
        int v = (t >= off) ? sm[t - off] : 0;
        __syncthreads();
        sm[t] += v;
        __syncthreads();
    }
    if (i < n) {
        int excl = g_boff[b] + sm[t] - d;
        g_rowptr[i] = excl;
        g_cursor[i] = excl;
        g_dinv[i] = (d > 0) ? rsqrtf((float)d) : 0.0f;
        if (i == n - 1) g_rowptr[n] = excl + d;
    }
}

// ---------------------------------------------------------------------------
// 4) scatter edges into CSR (4 edges/thread)
// ---------------------------------------------------------------------------
__global__ void scatter4_kernel(const int* __restrict__ row, const int* __restrict__ col,
                                const float* __restrict__ w, int e) {
    int i = (blockIdx.x * blockDim.x + threadIdx.x) * 4;
    if (i + 4 <= e) {
        int4 r = *reinterpret_cast<const int4*>(row + i);
        int4 c = *reinterpret_cast<const int4*>(col + i);
        float4 ww = *reinterpret_cast<const float4*>(w + i);
        float dr0 = g_dinv[r.x], dc0 = g_dinv[c.x];
        float dr1 = g_dinv[r.y], dc1 = g_dinv[c.y];
        float dr2 = g_dinv[r.z], dc2 = g_dinv[c.z];
        float dr3 = g_dinv[r.w], dc3 = g_dinv[c.w];
        if (r.x != c.x) {
            int p = atomicAdd(&g_cursor[r.x], 1);
            g_edge[p] = make_int2(c.x, __float_as_int(-dr0 * ww.x * dc0));
        }
        if (r.y != c.y) {
            int p = atomicAdd(&g_cursor[r.y], 1);
            g_edge[p] = make_int2(c.y, __float_as_int(-dr1 * ww.y * dc1));
        }
        if (r.z != c.z) {
            int p = atomicAdd(&g_cursor[r.z], 1);
            g_edge[p] = make_int2(c.z, __float_as_int(-dr2 * ww.z * dc2));
        }
        if (r.w != c.w) {
            int p = atomicAdd(&g_cursor[r.w], 1);
            g_edge[p] = make_int2(c.w, __float_as_int(-dr3 * ww.w * dc3));
        }
    } else {
        for (; i < e; ++i) {
            int r = row[i], c = col[i];
            if (r != c) {
                int p = atomicAdd(&g_cursor[r], 1);
                g_edge[p] = make_int2(c, __float_as_int(-g_dinv[r] * w[i] * g_dinv[c]));
            }
        }
    }
}

// ---------------------------------------------------------------------------
// 5) SpMM, fp16 gathers (register-safe convert), fp32 accumulate
//    pass 0: tx1 = L @ x   (gathers g_xh,  writes g_tx1 fp32 + g_t1h fp16)
//    pass 1: z   = L @ tx1 (gathers g_t1h, writes g_tx2 fp32)
// ---------------------------------------------------------------------------
__device__ __forceinline__ void hacc(float4& acc, float w, uint2 u) {
    float2 a = h2tof2(u.x);
    float2 b = h2tof2(u.y);
    acc.x = fmaf(w, a.x, acc.x); acc.y = fmaf(w, a.y, acc.y);
    acc.z = fmaf(w, b.x, acc.z); acc.w = fmaf(w, b.y, acc.w);
}

__global__ void spmm_kernel(int n, int pass) {
    int r = blockIdx.x * 8 + threadIdx.y;
    if (r >= n) return;
    int lane = threadIdx.x;  // 0..35

    const uint2* __restrict__ src = pass ? g_t1h : g_xh;

    int s = g_rowptr[r];
    int e = g_rowptr[r + 1];

    float4 acc = make_float4(0.f, 0.f, 0.f, 0.f);
    int i = s;
    for (; i + 4 <= e; i += 4) {
        int2 e0 = __ldg(&g_edge[i + 0]);
        int2 e1 = __ldg(&g_edge[i + 1]);
        int2 e2 = __ldg(&g_edge[i + 2]);
        int2 e3 = __ldg(&g_edge[i + 3]);
        uint2 u0 = __ldg(&src[(size_t)e0.x * 36 + lane]);
        uint2 u1 = __ldg(&src[(size_t)e1.x * 36 + lane]);
        uint2 u2 = __ldg(&src[(size_t)e2.x * 36 + lane]);
        uint2 u3 = __ldg(&src[(size_t)e3.x * 36 + lane]);
        hacc(acc, __int_as_float(e0.y), u0);
        hacc(acc, __int_as_float(e1.y), u1);
        hacc(acc, __int_as_float(e2.y), u2);
        hacc(acc, __int_as_float(e3.y), u3);
    }
    for (; i < e; ++i) {
        int2 ee = __ldg(&g_edge[i]);
        uint2 u = __ldg(&src[(size_t)ee.x * 36 + lane]);
        hacc(acc, __int_as_float(ee.y), u);
    }

    size_t o = (size_t)r * 36 + lane;
    if (pass) {
        g_tx2[o] = acc;                       // z = L*Tx1 (2x folded into wcat)
    } else {
        g_tx1[o] = acc;
        uint2 u;
        u.x = f2toh2(acc.x, acc.y);
        u.y = f2toh2(acc.z, acc.w);
        g_t1h[o] = u;
    }
}

// ---------------------------------------------------------------------------
// 6) fused GEMM: out[N,144] = [x|tx1|z] @ g_wcat + bias
//    BM=128, BK=24, 384 threads, 4x12 micro-tile, packed f32x2 FMA
// ---------------------------------------------------------------------------
#define BM 128
#define GT 384

__device__ __forceinline__ ull fdup(float v) {
    unsigned u = __float_as_uint(v);
    return (ull)u | ((ull)u << 32);
}
__device__ __forceinline__ void ffma2(ull& d, ull a, ull b) {
    asm("fma.rn.f32x2 %0, %1, %2, %0;" : "+l"(d) : "l"(a), "l"(b));
}

__global__ __launch_bounds__(GT) void gemm_kernel(const float* __restrict__ x,
                                                  const float* __restrict__ bias,
                                                  float* __restrict__ out, int n) {
    __shared__ __align__(16) ull   As[24 * 130];
    __shared__ __align__(16) float Bs[24 * 148];

    int tid = threadIdx.x;
    int m0 = blockIdx.x * BM;
    int cg = tid % 12;
    int rg = tid / 12;
    int colS = 12 * cg + ((cg >= 8) ? 2 : 0);
    int colG = 12 * cg;

    int qa0 = tid % 6,         ma0 = tid / 6;
    int qa1 = (GT + tid) % 6,  ma1 = (GT + tid) / 6;
    int physb[9];
#pragma unroll
    for (int p = 0; p < 9; ++p) {
        int idx = p * GT + tid;
        int j = idx % 144, kk = idx / 144;
        physb[p] = kk * 148 + j + ((j >= 96) ? 2 : 0);
    }

    ull acc[4][6];
#pragma unroll
    for (int r = 0; r < 4; ++r)
#pragma unroll
        for (int p = 0; p < 6; ++p) acc[r][p] = 0ull;

    const float* t1 = (const float*)g_tx1;
    const float* t2 = (const float*)g_tx2;

    float4 av0, av1;
    float bv[9];

    {   // prefetch kt = 0
        int gm0 = m0 + ma0, gm1 = m0 + ma1;
        av0 = (gm0 < n) ? *reinterpret_cast<const float4*>(x + (size_t)gm0 * 144 + 4 * qa0)
                        : make_float4(0.f, 0.f, 0.f, 0.f);
        av1 = (gm1 < n) ? *reinterpret_cast<const float4*>(x + (size_t)gm1 * 144 + 4 * qa1)
                        : make_float4(0.f, 0.f, 0.f, 0.f);
#pragma unroll
        for (int p = 0; p < 9; ++p) bv[p] = g_wcat[p * GT + tid];
    }

    for (int kt = 0; kt < 18; ++kt) {
        As[(4 * qa0 + 0) * 130 + ma0] = fdup(av0.x);
        As[(4 * qa0 + 1) * 130 + ma0] = fdup(av0.y);
        As[(4 * qa0 + 2) * 130 + ma0] = fdup(av0.z);
        As[(4 * qa0 + 3) * 130 + ma0] = fdup(av0.w);
        As[(4 * qa1 + 0) * 130 + ma1] = fdup(av1.x);
        As[(4 * qa1 + 1) * 130 + ma1] = fdup(av1.y);
        As[(4 * qa1 + 2) * 130 + ma1] = fdup(av1.z);
        As[(4 * qa1 + 3) * 130 + ma1] = fdup(av1.w);
#pragma unroll
        for (int p = 0; p < 9; ++p) Bs[physb[p]] = bv[p];
        __syncthreads();

        if (kt < 17) {
            int kn = kt + 1;
            int s = kn / 6;
            int kl = (kn % 6) * 24;
            const float* A = (s == 0) ? x : ((s == 1) ? t1 : t2);
            int gm0 = m0 + ma0, gm1 = m0 + ma1;
            av0 = (gm0 < n) ? *reinterpret_cast<const float4*>(A + (size_t)gm0 * 144 + kl + 4 * qa0)
                            : make_float4(0.f, 0.f, 0.f, 0.f);
            av1 = (gm1 < n) ? *reinterpret_cast<const float4*>(A + (size_t)gm1 * 144 + kl + 4 * qa1)
                            : make_float4(0.f, 0.f, 0.f, 0.f);
            const float* Wt = g_wcat + (size_t)kn * 3456;
#pragma unroll
            for (int p = 0; p < 9; ++p) bv[p] = __ldg(&Wt[p * GT + tid]);
        }

#pragma unroll
        for (int kk = 0; kk < 24; ++kk) {
            const ull* ar = &As[kk * 130 + rg * 4];
            ulonglong2 A01 = *reinterpret_cast<const ulonglong2*>(ar);
            ulonglong2 A23 = *reinterpret_cast<const ulonglong2*>(ar + 2);
            ull a0 = A01.x, a1 = A01.y, a2 = A23.x, a3 = A23.y;
            const float* bp = &Bs[kk * 148 + colS];
            ull b0 = *reinterpret_cast<const ull*>(bp);
            ull b1 = *reinterpret_cast<const ull*>(bp + 2);
            ull b2 = *reinterpret_cast<const ull*>(bp + 4);
            ull b3 = *reinterpret_cast<const ull*>(bp + 6);
            ull b4 = *reinterpret_cast<const ull*>(bp + 8);
            ull b5 = *reinterpret_cast<const ull*>(bp + 10);
            ffma2(acc[0][0], a0, b0); ffma2(acc[0][1], a0, b1); ffma2(acc[0][2], a0, b2);
            ffma2(acc[0][3], a0, b3); ffma2(acc[0][4], a0, b4); ffma2(acc[0][5], a0, b5);
            ffma2(acc[1][0], a1, b0); ffma2(acc[1][1], a1, b1); ffma2(acc[1][2], a1, b2);
            ffma2(acc[1][3], a1, b3); ffma2(acc[1][4], a1, b4); ffma2(acc[1][5], a1, b5);
            ffma2(acc[2][0], a2, b0); ffma2(acc[2][1], a2, b1); ffma2(acc[2][2], a2, b2);
            ffma2(acc[2][3], a2, b3); ffma2(acc[2][4], a2, b4); ffma2(acc[2][5], a2, b5);
            ffma2(acc[3][0], a3, b0); ffma2(acc[3][1], a3, b1); ffma2(acc[3][2], a3, b2);
            ffma2(acc[3][3], a3, b3); ffma2(acc[3][4], a3, b4); ffma2(acc[3][5], a3, b5);
        }
        __syncthreads();
    }

    float bl[12];
#pragma unroll
    for (int t = 0; t < 12; ++t) bl[t] = __ldg(&bias[colG + t]);

#pragma unroll
    for (int r = 0; r < 4; ++r) {
        int gm = m0 + rg * 4 + r;
        if (gm < n) {
            float* o = out + (size_t)gm * 144 + colG;
#pragma unroll
            for (int q = 0; q < 3; ++q) {
                ull p0 = acc[r][2 * q], p1 = acc[r][2 * q + 1];
                float4 v;
                v.x = __uint_as_float((unsigned)(p0 & 0xffffffffu)) + bl[4 * q + 0];
                v.y = __uint_as_float((unsigned)(p0 >> 32))         + bl[4 * q + 1];
                v.z = __uint_as_float((unsigned)(p1 & 0xffffffffu)) + bl[4 * q + 2];
                v.w = __uint_as_float((unsigned)(p1 >> 32))         + bl[4 * q + 3];
                *reinterpret_cast<float4*>(o + 4 * q) = v;
            }
        }
    }
}

// ---------------------------------------------------------------------------
// launcher
// ---------------------------------------------------------------------------
extern "C" void kernel_launch(void* const* d_in, const int* in_sizes, int n_in,
                              void* d_out, int out_size) {
    const float* x    = (const float*)d_in[0];   // [N, 144]
    const int*   ei   = (const int*)d_in[1];     // [2, E]
    const float* ew   = (const float*)d_in[2];   // [E]
    const float* wgt  = (const float*)d_in[3];   // [3, 144, 144]
    const float* bias = (const float*)d_in[4];   // [144]
    float* out = (float*)d_out;

    int n = in_sizes[0] / F;
    int e = in_sizes[2];
    const int* row = ei;
    const int* col = ei + e;
    int nb = (n + 511) / 512;

    prep_kernel<<<(n * 72 + 255) / 256, 256>>>(x, wgt, n);
    hist4_kernel<<<((e + 3) / 4 + 255) / 256, 256>>>(row, col, e);
    scanA_kernel<<<nb, 512>>>(n);
    scanB_kernel<<<1, 128>>>(nb);
    scanC_kernel<<<nb, 512>>>(n);
    scatter4_kernel<<<((e + 3) / 4 + 255) / 256, 256>>>(row, col, ew, e);

    dim3 sb(36, 8);
    spmm_kernel<<<(n + 7) / 8, sb>>>(n, 0);   // tx1 = L x    (fp16 gather)
    spmm_kernel<<<(n + 7) / 8, sb>>>(n, 1);   // z   = L tx1  (fp16 gather)

    gemm_kernel<<<(n + BM - 1) / BM, GT>>>(x, bias, out, n);
}